// round 8
// baseline (speedup 1.0000x reference)
#include <cuda_runtime.h>
#include <cstdint>

// FourStateQuantizer: elementwise soft quantization over {-1,-0.5,0.5,1}, T=0.3.
// q = [c2(u^4-1) + 0.5 c1 u(u^2-1)] / [c2(u^4+1) + c1 u(u^2+1)],  u = e^{x/T}
// (x^2 softmax term cancels; multiplied through by u^2). Clamp x at +6.
// 2 MUFU/elem (EX2 + RCP-divide).
//
// R8: H2 test — decouple the read stream from compute. cp.async.bulk (UBLKCP)
// fills a 3-stage x 12KB smem ring per CTA with mbarrier tx-completion; the
// bulk engine keeps reads in flight with no register/MUFU coupling, so DRAM
// request supply never breathes. Consumers LDS.128 -> quant -> STG.128.
// 36KB smem/CTA -> 6 CTA/SM (48 warps, 75% occ).

#define TPB      256
#define STAGES   3
#define STAGE_F4 768                 // 12KB per stage, 3 float4 per thread
#define ITERS    8                   // stages per CTA -> 6144 float4/CTA

__device__ __forceinline__ uint32_t smem_u32(const void* p) {
    return (uint32_t)__cvta_generic_to_shared(p);
}

__device__ __forceinline__ void mbar_wait_parity(uint32_t mb, uint32_t parity) {
    asm volatile(
        "{\n\t"
        ".reg .pred P;\n\t"
        "WL_%=:\n\t"
        "mbarrier.try_wait.parity.acquire.cta.shared::cta.b64 P, [%0], %1, 0x989680;\n\t"
        "@P bra.uni WD_%=;\n\t"
        "bra.uni WL_%=;\n\t"
        "WD_%=:\n\t"
        "}"
        :: "r"(mb), "r"(parity) : "memory");
}

__device__ __forceinline__ float quant1(float x) {
    const float K   = 4.80898346962988f;     // log2(e)/0.3
    const float C1H = 0.2172991042535391f;   // 0.5*exp(-0.25/0.3)
    const float C2  = 0.03567399334725241f;  // exp(-1.0/0.3)
    x = fminf(x, 6.0f);
    float u  = exp2f(x * K);                 // MUFU.EX2
    float u2 = u * u;
    float u4 = u2 * u2;
    float w1 = C1H * u;
    float w2 = w1 + w1;
    float num = fmaf(w1, u2 - 1.0f, fmaf(C2, u4, -C2));
    float den = fmaf(w2, u2 + 1.0f, fmaf(C2, u4,  C2));
    return __fdividef(num, den);             // MUFU.RCP + FMUL
}

__device__ __forceinline__ float4 quant4(float4 x) {
    float4 q;
    q.x = quant1(x.x); q.y = quant1(x.y);
    q.z = quant1(x.z); q.w = quant1(x.w);
    return q;
}

__global__ __launch_bounds__(TPB, 6) void fourstate_pipe(
    const float4* __restrict__ in, float4* __restrict__ out)
{
    __shared__ __align__(16) float4   buf[STAGES][STAGE_F4];
    __shared__ __align__(8)  uint64_t mb_full[STAGES];
    __shared__ __align__(8)  uint64_t mb_empty[STAGES];

    const int tid = threadIdx.x;
    if (tid == 0) {
        #pragma unroll
        for (int s = 0; s < STAGES; s++) {
            asm volatile("mbarrier.init.shared.b64 [%0], %1;"
                         :: "r"(smem_u32(&mb_full[s])), "r"(1) : "memory");
            asm volatile("mbarrier.init.shared.b64 [%0], %1;"
                         :: "r"(smem_u32(&mb_empty[s])), "r"(TPB) : "memory");
        }
        asm volatile("fence.proxy.async.shared::cta;" ::: "memory");
    }
    __syncthreads();

    const size_t cta_base = (size_t)blockIdx.x * (ITERS * STAGE_F4);

    // Prologue: fill all stages (bulk engine runs ahead of compute from cycle 0).
    if (tid == 0) {
        #pragma unroll
        for (int s = 0; s < STAGES; s++) {
            uint32_t mf = smem_u32(&mb_full[s]);
            asm volatile("mbarrier.arrive.expect_tx.shared.b64 _, [%0], %1;"
                         :: "r"(mf), "r"(STAGE_F4 * 16) : "memory");
            asm volatile(
                "cp.async.bulk.shared::cta.global.mbarrier::complete_tx::bytes "
                "[%0], [%1], %2, [%3];"
                :: "r"(smem_u32(&buf[s][0])),
                   "l"(in + cta_base + (size_t)s * STAGE_F4),
                   "r"(STAGE_F4 * 16), "r"(mf) : "memory");
        }
    }

    for (int it = 0; it < ITERS; it++) {
        const int s  = it % STAGES;
        const uint32_t ph = (uint32_t)((it / STAGES) & 1);

        mbar_wait_parity(smem_u32(&mb_full[s]), ph);

        float4 x0 = buf[s][tid];
        float4 x1 = buf[s][tid + TPB];
        float4 x2 = buf[s][tid + 2 * TPB];
        float4 q0 = quant4(x0);
        float4 q1 = quant4(x1);
        float4 q2 = quant4(x2);
        size_t g = cta_base + (size_t)it * STAGE_F4 + tid;
        out[g]           = q0;
        out[g + TPB]     = q1;
        out[g + 2 * TPB] = q2;

        asm volatile("mbarrier.arrive.shared.b64 _, [%0];"
                     :: "r"(smem_u32(&mb_empty[s])) : "memory");

        if (tid == 0) {
            const int nit = it + STAGES;
            if (nit < ITERS) {
                // wait this round's consumption of stage s, then refill it
                mbar_wait_parity(smem_u32(&mb_empty[s]), ph);
                uint32_t mf = smem_u32(&mb_full[s]);
                asm volatile("mbarrier.arrive.expect_tx.shared.b64 _, [%0], %1;"
                             :: "r"(mf), "r"(STAGE_F4 * 16) : "memory");
                asm volatile(
                    "cp.async.bulk.shared::cta.global.mbarrier::complete_tx::bytes "
                    "[%0], [%1], %2, [%3];"
                    :: "r"(smem_u32(&buf[s][0])),
                       "l"(in + cta_base + (size_t)nit * STAGE_F4),
                       "r"(STAGE_F4 * 16), "r"(mf) : "memory");
            }
        }
    }
}

// Scalar tail for any remainder not covered by full CTAs (empty for this size).
__global__ void fourstate_tail(const float4* __restrict__ in,
                               float4* __restrict__ out, int start, int n4)
{
    int i = start + blockIdx.x * blockDim.x + threadIdx.x;
    if (i < n4) out[i] = quant4(in[i]);
}

extern "C" void kernel_launch(void* const* d_in, const int* in_sizes, int n_in,
                              void* d_out, int out_size) {
    const float4* in = (const float4*)d_in[0];
    float4* out = (float4*)d_out;
    int n  = in_sizes[0];                 // 50,331,648
    int n4 = n >> 2;                      // 12,582,912 float4s
    const int per_cta = ITERS * STAGE_F4; // 6144 float4 per CTA
    int blocks = n4 / per_cta;            // 2048, exact
    if (blocks > 0)
        fourstate_pipe<<<blocks, TPB>>>(in, out);
    int done = blocks * per_cta;
    int rem  = n4 - done;                 // 0 for this problem size
    if (rem > 0)
        fourstate_tail<<<(rem + 255) / 256, 256>>>(in, out, done, n4);
}

// round 9
// speedup vs baseline: 1.0756x; 1.0756x over previous
#include <cuda_runtime.h>

// FourStateQuantizer: elementwise soft quantization over states {-1,-0.5,0.5,1}, T=0.3.
// softmax(-(x-s)^2/T): x^2 cancels -> w_i ∝ exp((2 s_i x - s_i^2)/T). With u = e^{x/T},
// multiply num/den by u^2 -> polynomials in u only:
//   q = [c2(u^4-1) + 0.5 c1 u(u^2-1)] / [c2(u^4+1) + c1 u(u^2+1)]
// Clamp x at +6 (q(6)=1-1.2e-8; keeps u^4 finite); u->0 side safe (q->-1).
// 2 MUFU/elem (EX2 + RCP-divide).
//
// R9: R4's proven shape (TPB=256, 4 front-batched LDG.128, occ~82%) + __stcs on
// STORES ONLY. ncu showed ~13% of traffic served from L2 (input residency);
// evict-first on the write-once output stream protects that residency. Loads
// stay default (R5 showed .cs on loads hurts).

__device__ __forceinline__ float quant1(float x) {
    const float K   = 4.80898346962988f;     // log2(e)/0.3
    const float C1H = 0.2172991042535391f;   // 0.5*exp(-0.25/0.3)
    const float C2  = 0.03567399334725241f;  // exp(-1.0/0.3)
    x = fminf(x, 6.0f);
    float u  = exp2f(x * K);                 // MUFU.EX2
    float u2 = u * u;
    float u4 = u2 * u2;
    float w1 = C1H * u;                      // 0.5*c1*u
    float w2 = w1 + w1;                      // c1*u
    float num = fmaf(w1, u2 - 1.0f, fmaf(C2, u4, -C2));
    float den = fmaf(w2, u2 + 1.0f, fmaf(C2, u4,  C2));
    return __fdividef(num, den);             // MUFU.RCP + FMUL
}

__device__ __forceinline__ float4 quant4(float4 x) {
    float4 q;
    q.x = quant1(x.x); q.y = quant1(x.y);
    q.z = quant1(x.z); q.w = quant1(x.w);
    return q;
}

#define TPB    256
#define UNROLL 4

__global__ __launch_bounds__(TPB) void fourstate_kernel(
    const float4* __restrict__ in, float4* __restrict__ out, int n4)
{
    int base = blockIdx.x * (TPB * UNROLL) + threadIdx.x;
    if (base + (UNROLL - 1) * TPB < n4) {
        // fast path (exact for this problem size): 4 front-batched LDG.128
        float4 x0 = in[base];
        float4 x1 = in[base + TPB];
        float4 x2 = in[base + 2 * TPB];
        float4 x3 = in[base + 3 * TPB];
        float4 q0 = quant4(x0);
        float4 q1 = quant4(x1);
        float4 q2 = quant4(x2);
        float4 q3 = quant4(x3);
        __stcs(&out[base],           q0);   // evict-first: output is never re-read
        __stcs(&out[base + TPB],     q1);
        __stcs(&out[base + 2 * TPB], q2);
        __stcs(&out[base + 3 * TPB], q3);
    } else {
        #pragma unroll
        for (int j = 0; j < UNROLL; j++) {
            int i = base + j * TPB;
            if (i < n4) __stcs(&out[i], quant4(in[i]));
        }
    }
}

extern "C" void kernel_launch(void* const* d_in, const int* in_sizes, int n_in,
                              void* d_out, int out_size) {
    const float4* in = (const float4*)d_in[0];
    float4* out = (float4*)d_out;
    int n  = in_sizes[0];                 // 50,331,648
    int n4 = n >> 2;                      // 12,582,912 float4s
    int per_block = TPB * UNROLL;         // 1024 float4s per block
    int blocks = (n4 + per_block - 1) / per_block;   // 12288, exact
    fourstate_kernel<<<blocks, TPB>>>(in, out, n4);
}